// round 16
// baseline (speedup 1.0000x reference)
#include <cuda_runtime.h>
#include <cuda_fp16.h>

#define NN 100000
#define EE 3200000
#define IN_DIM 256
#define H1 32
#define H2 64

typedef unsigned long long ull;

// ---- packed f32x2 helpers (Blackwell FFMA2) --------------------------------
__device__ __forceinline__ ull ffma2(ull a, ull b, ull c) {
    ull d;
    asm("fma.rn.f32x2 %0, %1, %2, %3;" : "=l"(d) : "l"(a), "l"(b), "l"(c));
    return d;
}
__device__ __forceinline__ float2 unpack2(ull v) {
    float2 r;
    asm("mov.b64 {%0, %1}, %2;" : "=f"(r.x), "=f"(r.y) : "l"(v));
    return r;
}

// ---- tf32 mma helpers -------------------------------------------------------
__device__ __forceinline__ unsigned cvt_tf32(float f) {
    unsigned u;
    asm("cvt.rna.tf32.f32 %0, %1;" : "=r"(u) : "f"(f));
    return u;
}
__device__ __forceinline__ void mma_tf32(float c[4], unsigned a0, unsigned a1,
                                         unsigned a2, unsigned a3,
                                         unsigned b0, unsigned b1) {
    asm("mma.sync.aligned.m16n8k8.row.col.f32.tf32.tf32.f32 "
        "{%0,%1,%2,%3},{%4,%5,%6,%7},{%8,%9},{%0,%1,%2,%3};"
        : "+f"(c[0]), "+f"(c[1]), "+f"(c[2]), "+f"(c[3])
        : "r"(a0), "r"(a1), "r"(a2), "r"(a3), "r"(b0), "r"(b1));
}

// ---------------- static device scratch -------------------------------------
__device__ __align__(256) float   g_h1[NN * H1];   // x@W1 (fp32, unscaled)
__device__ __align__(256) __half2 g_h1h[NN * 16];  // scaled h1, pairs (c, c+16)
__device__ __align__(256) __half2 g_h2h[NN * 32];  // (z1@W2)*dinv, pairs (c, c+32)
__device__ __align__(256) __half  g_z2h[NN * 64];  // z2, row-major fp16
__device__ int   g_cnt[NN];
__device__ int   g_rowptr[NN + 1];
__device__ int   g_col[EE];
__device__ int   g_off[EE];     // per-edge within-row slot (from hist)
__device__ float g_dinv[NN];
__device__ int   g_bsum[256];
__device__ float g_part[2048];
__device__ float g_scalar[2];
__device__ int   g_flag;        // 1 if edge index int64, 0 if int32

// ------------- zero counters + detect edge dtype ----------------------------
__global__ void detect_zero_kernel(const unsigned int* __restrict__ w, int n_vals, int N) {
    int i = blockIdx.x * blockDim.x + threadIdx.x;
    if (i < N) g_cnt[i] = 0;
    if (blockIdx.x == 0) {
        __shared__ unsigned int acc;
        if (threadIdx.x == 0) acc = 0u;
        __syncthreads();
        int K = n_vals < 2048 ? n_vals : 2048;
        unsigned int v = 0u;
        for (int j = threadIdx.x; j < K; j += blockDim.x) v |= w[2 * j + 1];
        atomicOr(&acc, v);
        __syncthreads();
        if (threadIdx.x == 0) g_flag = (acc == 0u) ? 1 : 0;
    }
}

// ------------- histogram of dst (2 edges/thread) + per-edge slot ------------
__global__ void hist_kernel(const int* __restrict__ buf, int E) {
    int e = (blockIdx.x * blockDim.x + threadIdx.x) * 2;
    if (e + 1 < E) {
        int d0, d1;
        if (g_flag) { int4 v = *(const int4*)&buf[2 * (E + e)]; d0 = v.x; d1 = v.z; }
        else        { int2 v = *(const int2*)&buf[E + e];       d0 = v.x; d1 = v.y; }
        int p0 = atomicAdd(&g_cnt[d0], 1);
        int p1 = atomicAdd(&g_cnt[d1], 1);
        *(int2*)&g_off[e] = make_int2(p0, p1);
    } else if (e < E) {
        int d = g_flag ? buf[2 * (E + e)] : buf[E + e];
        g_off[e] = atomicAdd(&g_cnt[d], 1);
    }
}

__global__ void hist_kernel_s(const int* __restrict__ buf, int E) {
    int e = blockIdx.x * blockDim.x + threadIdx.x;
    if (e < E) {
        int d = g_flag ? buf[2 * (E + e)] : buf[E + e];
        g_off[e] = atomicAdd(&g_cnt[d], 1);
    }
}

// ------------- scan stage 1: per-chunk exclusive prefix + chunk totals ------
__global__ void scan1_kernel(int N) {
    __shared__ int sm[1024];
    int t = threadIdx.x;
    int i = blockIdx.x * 1024 + t;
    int x = (i < N) ? g_cnt[i] : 0;
    sm[t] = x;
    __syncthreads();
    for (int off = 1; off < 1024; off <<= 1) {
        int v = (t >= off) ? sm[t - off] : 0;
        __syncthreads();
        sm[t] += v;
        __syncthreads();
    }
    if (i < N) g_rowptr[i] = sm[t] - x;
    if (t == 1023) g_bsum[blockIdx.x] = sm[1023];
}

// ------------- scan stage 2 (merged): chunk-offset reduce + rowptr + dinv ---
__global__ void scan3a_kernel(int N, int E) {
    __shared__ int red[256];
    int t = threadIdx.x;
    int chunk = (blockIdx.x * 256) >> 10;
    red[t] = (t < chunk) ? g_bsum[t] : 0;
    __syncthreads();
    #pragma unroll
    for (int off = 128; off > 0; off >>= 1) {
        if (t < off) red[t] += red[t + off];
        __syncthreads();
    }
    int S = red[0];
    int i = blockIdx.x * 256 + t;
    if (i < N) {
        g_rowptr[i] = g_rowptr[i] + S;
        g_dinv[i]   = rsqrtf((float)(g_cnt[i] + 1));
        if (i == 0) g_rowptr[N] = E;
    }
}

// pack_h1: scale by dinv and pack to fp16 pairs (side stream, overlaps fill)
__global__ void pack_h1_kernel(int N) {
    int i = blockIdx.x * blockDim.x + threadIdx.x;
    if (i < N) {
        float di = g_dinv[i];
        float ch[32];
        const float4* h = (const float4*)&g_h1[i * H1];
        #pragma unroll
        for (int j = 0; j < 8; j++) {
            float4 v = h[j];
            ch[4 * j + 0] = v.x * di; ch[4 * j + 1] = v.y * di;
            ch[4 * j + 2] = v.z * di; ch[4 * j + 3] = v.w * di;
        }
        #pragma unroll
        for (int p = 0; p < 16; p++)
            g_h1h[i * 16 + p] = __floats2half2_rn(ch[p], ch[p + 16]);
    }
}

// ------------- GEMM1 via tf32 tensor cores (side stream) --------------------
__global__ void gemm1_kernel(const float* __restrict__ x,
                             const float* __restrict__ W1, int N) {
    __shared__ unsigned Bs[8192];   // [ks][nf][j][lane], 32 KB
    int t = threadIdx.x;
    for (int i = t; i < 8192; i += 256) {
        int lane2 = i & 31;
        int j  = (i >> 5) & 1;
        int nf = (i >> 6) & 3;
        int ks = i >> 8;
        int k = ks * 8 + (lane2 & 3) + j * 4;
        int n = nf * 8 + (lane2 >> 2);
        Bs[i] = cvt_tf32(W1[k * 32 + n]);
    }
    __syncthreads();
    int lane = t & 31, wid = t >> 5;
    int qrow = lane >> 2, qk = lane & 3;
    long r0 = (long)(blockIdx.x * 8 + wid) * 32;
    if (r0 >= N) return;
    long NL = N - 1;
    const float* p0 = x + (r0 + qrow      <= NL ? r0 + qrow      : NL) * 256 + qk;
    const float* p1 = x + (r0 + qrow + 8  <= NL ? r0 + qrow + 8  : NL) * 256 + qk;
    const float* p2 = x + (r0 + qrow + 16 <= NL ? r0 + qrow + 16 : NL) * 256 + qk;
    const float* p3 = x + (r0 + qrow + 24 <= NL ? r0 + qrow + 24 : NL) * 256 + qk;
    float c0[4][4] = {}, c1[4][4] = {};
    #pragma unroll 4
    for (int ks = 0; ks < 32; ks++) {
        int k0 = ks * 8;
        const unsigned* bp = &Bs[ks * 256 + lane];
        unsigned b00 = bp[0],   b01 = bp[32];
        unsigned b10 = bp[64],  b11 = bp[96];
        unsigned b20 = bp[128], b21 = bp[160];
        unsigned b30 = bp[192], b31 = bp[224];
        unsigned a0 = cvt_tf32(p0[k0]);
        unsigned a1 = cvt_tf32(p1[k0]);
        unsigned a2 = cvt_tf32(p0[k0 + 4]);
        unsigned a3 = cvt_tf32(p1[k0 + 4]);
        mma_tf32(c0[0], a0, a1, a2, a3, b00, b01);
        mma_tf32(c0[1], a0, a1, a2, a3, b10, b11);
        mma_tf32(c0[2], a0, a1, a2, a3, b20, b21);
        mma_tf32(c0[3], a0, a1, a2, a3, b30, b31);
        a0 = cvt_tf32(p2[k0]);
        a1 = cvt_tf32(p3[k0]);
        a2 = cvt_tf32(p2[k0 + 4]);
        a3 = cvt_tf32(p3[k0 + 4]);
        mma_tf32(c1[0], a0, a1, a2, a3, b00, b01);
        mma_tf32(c1[1], a0, a1, a2, a3, b10, b11);
        mma_tf32(c1[2], a0, a1, a2, a3, b20, b21);
        mma_tf32(c1[3], a0, a1, a2, a3, b30, b31);
    }
    long rw0 = r0 + qrow, rw1 = rw0 + 8, rw2 = rw0 + 16, rw3 = rw0 + 24;
    int cb = 2 * qk;
    #pragma unroll
    for (int nf = 0; nf < 4; nf++) {
        int col = nf * 8 + cb;
        if (rw0 < N) *(float2*)&g_h1[rw0 * 32 + col] = make_float2(c0[nf][0], c0[nf][1]);
        if (rw1 < N) *(float2*)&g_h1[rw1 * 32 + col] = make_float2(c0[nf][2], c0[nf][3]);
        if (rw2 < N) *(float2*)&g_h1[rw2 * 32 + col] = make_float2(c1[nf][0], c1[nf][1]);
        if (rw3 < N) *(float2*)&g_h1[rw3 * 32 + col] = make_float2(c1[nf][2], c1[nf][3]);
    }
}

// ------------- CSR fill (atomic-free: slot precomputed by hist) -------------
__global__ void fill_kernel(const int* __restrict__ buf, int E) {
    int e = (blockIdx.x * blockDim.x + threadIdx.x) * 2;
    if (e + 1 < E) {
        int s0, s1, d0, d1;
        if (g_flag) {
            int4 sv = *(const int4*)&buf[2 * e];        s0 = sv.x; s1 = sv.z;
            int4 dv = *(const int4*)&buf[2 * (E + e)];  d0 = dv.x; d1 = dv.z;
        } else {
            int2 sv = *(const int2*)&buf[e];        s0 = sv.x; s1 = sv.y;
            int2 dv = *(const int2*)&buf[E + e];    d0 = dv.x; d1 = dv.y;
        }
        int2 o = *(const int2*)&g_off[e];
        g_col[g_rowptr[d0] + o.x] = s0;
        g_col[g_rowptr[d1] + o.y] = s1;
    } else if (e < E) {
        int s, d;
        if (g_flag) { d = buf[2 * (E + e)]; s = buf[2 * e]; }
        else        { d = buf[E + e];       s = buf[e]; }
        g_col[g_rowptr[d] + g_off[e]] = s;
    }
}

__global__ void fill_kernel_s(const int* __restrict__ buf, int E) {
    int e = blockIdx.x * blockDim.x + threadIdx.x;
    if (e < E) {
        int s, d;
        if (g_flag) { d = buf[2 * (E + e)]; s = buf[2 * e]; }
        else        { d = buf[E + e];       s = buf[e]; }
        g_col[g_rowptr[d] + g_off[e]] = s;
    }
}

// ------------- agg1: one node/warp; pipelined col loads; GEMV (smem FFMA2) --
__global__ void agg1_gemm2_kernel(const float* __restrict__ b1,
                                  const float* __restrict__ W2, int N) {
    __shared__ float2 Wp[H1 * 32];   // Wp[k*32+c] = (W2[k][c], W2[k][c+32])
    __shared__ float2 zd[8][32];     // duplicated z pairs per warp
    int t = threadIdx.x;
    for (int i = t; i < H1 * 32; i += blockDim.x) {
        int k = i >> 5, c2 = i & 31;
        Wp[i] = make_float2(W2[k * H2 + c2], W2[k * H2 + 32 + c2]);
    }
    __syncthreads();
    int lane = t & 31, wid = t >> 5;
    int c = lane & 15;
    int hb = (lane >> 4) << 4;   // 0 or 16
    int d = blockIdx.x * 8 + wid;
    if (d >= N) return;
    float bias0 = b1[c], bias1 = b1[c + 16];
    int beg = g_rowptr[d], end = g_rowptr[d + 1];
    float aAx = 0.f, aAy = 0.f, aBx = 0.f, aBy = 0.f;
    int e = beg;
    int cv = (e + 32 <= end) ? g_col[e + lane] : 0;   // preload block 0
    for (; e + 32 <= end; ) {
        int cur = cv;
        int en = e + 32;
        if (en + 32 <= end) cv = g_col[en + lane];    // prefetch next block
        #pragma unroll
        for (int j = 0; j < 16; j += 2) {
            int s0 = __shfl_sync(0xffffffffu, cur, j + hb);
            int s1 = __shfl_sync(0xffffffffu, cur, j + 1 + hb);
            float2 f0 = __half22float2(g_h1h[s0 * 16 + c]);
            float2 f1 = __half22float2(g_h1h[s1 * 16 + c]);
            aAx += f0.x; aAy += f0.y;
            aBx += f1.x; aBy += f1.y;
        }
        e = en;
    }
    if (e < end) {
        int n = end - e;
        int rv = (e + lane < end) ? g_col[e + lane] : 0;
        int hodd = hb >> 4;                  // 0 or 1
        for (int j = 0; j < n; j += 2) {
            int idx = j + hodd;
            int s = __shfl_sync(0xffffffffu, rv, idx < n ? idx : 0);
            if (idx < n) {
                float2 f = __half22float2(g_h1h[s * 16 + c]);
                aAx += f.x; aAy += f.y;
            }
        }
    }
    float ax = aAx + aBx, ay = aAy + aBy;
    ax += __shfl_xor_sync(0xffffffffu, ax, 16);
    ay += __shfl_xor_sync(0xffffffffu, ay, 16);
    float2 sf = __half22float2(g_h1h[d * 16 + c]);   // self loop
    float di = g_dinv[d];
    float z0  = fmaxf(di * (ax + sf.x) + bias0, 0.f);
    float z16 = fmaxf(di * (ay + sf.y) + bias1, 0.f);
    zd[wid][c]      = make_float2(z0, z0);
    zd[wid][c + 16] = make_float2(z16, z16);
    __syncwarp();
    ull a2 = 0;
    #pragma unroll
    for (int k = 0; k < 32; k++)
        a2 = ffma2(*(const ull*)&zd[wid][k], *(const ull*)&Wp[k * 32 + lane], a2);
    float2 a = unpack2(a2);
    g_h2h[d * 32 + lane] = __floats2half2_rn(a.x * di, a.y * di);
}

// ------------- agg2: one node/warp; pipelined col loads -> z2 ---------------
__global__ void agg2_kernel(const float* __restrict__ b2, int N) {
    __shared__ float bb[64];
    int t = threadIdx.x;
    if (t < 64) bb[t] = b2[t];
    __syncthreads();
    int lane = t & 31, wid = t >> 5;
    int d = blockIdx.x * 8 + wid;
    if (d >= N) return;
    float bias0 = bb[lane], bias1 = bb[lane + 32];
    int beg = g_rowptr[d], end = g_rowptr[d + 1];
    float2 self = __half22float2(g_h2h[d * 32 + lane]);
    float a00 = self.x, a10 = self.y;
    float a01 = 0.f, a11 = 0.f;
    int e = beg;
    int cv = (e + 32 <= end) ? g_col[e + lane] : 0;   // preload block 0
    for (; e + 32 <= end; ) {
        int cur = cv;
        int en = e + 32;
        if (en + 32 <= end) cv = g_col[en + lane];    // prefetch next block
        #pragma unroll
        for (int j = 0; j < 32; j += 2) {
            int s0 = __shfl_sync(0xffffffffu, cur, j);
            int s1 = __shfl_sync(0xffffffffu, cur, j + 1);
            float2 f0 = __half22float2(g_h2h[s0 * 32 + lane]);
            float2 f1 = __half22float2(g_h2h[s1 * 32 + lane]);
            a00 += f0.x; a10 += f0.y;
            a01 += f1.x; a11 += f1.y;
        }
        e = en;
    }
    if (e < end) {
        int n = end - e;
        int rv = (e + lane < end) ? g_col[e + lane] : 0;
        int j = 0;
        for (; j + 2 <= n; j += 2) {          // 2 edges per iteration
            int s0 = __shfl_sync(0xffffffffu, rv, j);
            int s1 = __shfl_sync(0xffffffffu, rv, j + 1);
            float2 f0 = __half22float2(g_h2h[s0 * 32 + lane]);
            float2 f1 = __half22float2(g_h2h[s1 * 32 + lane]);
            a00 += f0.x; a10 += f0.y;
            a01 += f1.x; a11 += f1.y;
        }
        if (j < n) {
            int s = __shfl_sync(0xffffffffu, rv, j);
            float2 f = __half22float2(g_h2h[s * 32 + lane]);
            a00 += f.x; a10 += f.y;
        }
    }
    float di = g_dinv[d];
    float t0 = fmaxf(di * (a00 + a01) + bias0, 0.f);
    float t1 = fmaxf(di * (a10 + a11) + bias1, 0.f);
    g_z2h[d * 64 + lane]      = __float2half_rn(t0);
    g_z2h[d * 64 + 32 + lane] = __float2half_rn(t1);
}

// ------------- MLP head via tf32 MMA: out = exp(relu(z2@Wo1+bo1)@Wo2+bo2) ---
#define UPITCH 68
#define MLP_SMEM (8192 * 4 + 8 * 32 * UPITCH * 4 + 128 * 4)
__global__ __launch_bounds__(256, 2)
void mlp_mma_kernel(const float* __restrict__ Wo1, const float* __restrict__ bo1,
                    const float* __restrict__ Wo2, const float* __restrict__ bo2,
                    float* __restrict__ out, int N) {
    extern __shared__ unsigned msm[];
    unsigned* Bs1 = msm;                         // 4096 u32
    unsigned* Bs2 = msm + 4096;                  // 4096 u32
    float* us  = (float*)(msm + 8192);           // 8 * 32 * 68 floats
    float* b1s = us + 8 * 32 * UPITCH;           // 64
    float* b2s = b1s + 64;                       // 64
    __shared__ float wsum[8];
    int t = threadIdx.x;
    for (int i = t; i < 4096; i += 256) {
        int lane2 = i & 31;
        int j  = (i >> 5) & 1;
        int nf = (i >> 6) & 7;
        int ks = (i >> 9) & 7;
        int k = ks * 8 + (lane2 & 3) + j * 4;
        int n = nf * 8 + (lane2 >> 2);
        Bs1[i] = cvt_tf32(Wo1[k * 64 + n]);
        Bs2[i] = cvt_tf32(Wo2[k * 64 + n]);
    }
    if (t < 64) { b1s[t] = bo1[t]; b2s[t] = bo2[t]; }
    __syncthreads();
    int lane = t & 31, wid = t >> 5;
    int qrow = lane >> 2, qk = lane & 3;
    long base = (long)(blockIdx.x * 8 + wid) * 32;
    float ssum = 0.f;
    if (base < N) {
        long NL = N - 1;
        long r0 = base + qrow      <= NL ? base + qrow      : NL;
        long r1 = base + qrow + 8  <= NL ? base + qrow + 8  : NL;
        long r2 = base + qrow + 16 <= NL ? base + qrow + 16 : NL;
        long r3 = base + qrow + 24 <= NL ? base + qrow + 24 : NL;
        float c0[8][4] = {}, c1[8][4] = {};
        #pragma unroll
        for (int ks = 0; ks < 8; ks++) {
            int k0 = ks * 8;
            unsigned a0 = cvt_tf32(__half2float(g_z2h[r0 * 64 + k0 + qk]));
            unsigned a1 = cvt_tf32(__half2float(g_z2h[r1 * 64 + k0 + qk]));
            unsigned a2 = cvt_tf32(__half2float(g_z2h[r0 * 64 + k0 + qk + 4]));
            unsigned a3 = cvt_tf32(__half2float(g_z2h[r1 * 64 + k0 + qk + 4]));
            unsigned a4 = cvt_tf32(__half2float(g_z2h[r2 * 64 + k0 + qk]));
            unsigned a5 = cvt_tf32(__half2float(g_z2h[r3 * 64 + k0 + qk]));
            unsigned a6 = cvt_tf32(__half2float(g_z2h[r2 * 64 + k0 + qk + 4]));
            unsigned a7 = cvt_tf32(__half2float(g_z2h[r3 * 64 + k0 + qk + 4]));
            const unsigned* bp = &Bs1[ks * 512 + lane];
            #pragma unroll
            for (int nf = 0; nf < 8; nf++) {
                unsigned b0 = bp[nf * 64], b1 = bp[nf * 64 + 32];
                mma_tf32(c0[nf], a0, a1, a2, a3, b0, b1);
                mma_tf32(c1[nf], a4, a5, a6, a7, b0, b1);
            }
        }
        float* uw = us + wid * (32 * UPITCH);
        #pragma unroll
        for (int nf = 0; nf < 8; nf++) {
            int col = nf * 8 + 2 * qk;
            float bb0 = b1s[col], bb1 = b1s[col + 1];
            uw[qrow * UPITCH + col]            = fmaxf(c0[nf][0] + bb0, 0.f);
            uw[qrow * UPITCH + col + 1]        = fmaxf(c0[nf][1] + bb1, 0.f);
            uw[(qrow + 8) * UPITCH + col]      = fmaxf(c0[nf][2] + bb0, 0.f);
            uw[(qrow + 8) * UPITCH + col + 1]  = fmaxf(c0[nf][3] + bb1, 0.f);
            uw[(qrow + 16) * UPITCH + col]     = fmaxf(c1[nf][0] + bb0, 0.f);
            uw[(qrow + 16) * UPITCH + col + 1] = fmaxf(c1[nf][1] + bb1, 0.f);
            uw[(qrow + 24) * UPITCH + col]     = fmaxf(c1[nf][2] + bb0, 0.f);
            uw[(qrow + 24) * UPITCH + col + 1] = fmaxf(c1[nf][3] + bb1, 0.f);
        }
        __syncwarp();
        float d0[8][4] = {}, d1[8][4] = {};
        #pragma unroll
        for (int ks = 0; ks < 8; ks++) {
            int k0 = ks * 8;
            unsigned a0 = cvt_tf32(uw[qrow * UPITCH + k0 + qk]);
            unsigned a1 = cvt_tf32(uw[(qrow + 8) * UPITCH + k0 + qk]);
            unsigned a2 = cvt_tf32(uw[qrow * UPITCH + k0 + qk + 4]);
            unsigned a3 = cvt_tf32(uw[(qrow + 8) * UPITCH + k0 + qk + 4]);
            unsigned a4 = cvt_tf32(uw[(qrow + 16) * UPITCH + k0 + qk]);
            unsigned a5 = cvt_tf32(uw[(qrow + 24) * UPITCH + k0 + qk]);
            unsigned a6 = cvt_tf32(uw[(qrow + 16) * UPITCH + k0 + qk + 4]);
            unsigned a7 = cvt_tf32(uw[(qrow + 24) * UPITCH + k0 + qk + 4]);
            const unsigned* bp = &Bs2[ks * 512 + lane];
            #pragma unroll
            for (int nf = 0; nf < 8; nf++) {
                unsigned b0 = bp[nf * 64], b1 = bp[nf * 64 + 32];
                mma_tf32(d0[nf], a0, a1, a2, a3, b0, b1);
                mma_tf32(d1[nf], a4, a5, a6, a7, b0, b1);
            }
        }
        #pragma unroll
        for (int nf = 0; nf < 8; nf++) {
            int col = nf * 8 + 2 * qk;
            float bb0 = b2s[col], bb1 = b2s[col + 1];
            long rw = base + qrow;
            float e0 = __expf(d0[nf][0] + bb0), e1 = __expf(d0[nf][1] + bb1);
            if (rw < N) { *(float2*)&out[rw * 64 + col] = make_float2(e0, e1); ssum += e0 + e1; }
            rw = base + qrow + 8;
            e0 = __expf(d0[nf][2] + bb0); e1 = __expf(d0[nf][3] + bb1);
            if (rw < N) { *(float2*)&out[rw * 64 + col] = make_float2(e0, e1); ssum += e0 + e1; }
            rw = base + qrow + 16;
            e0 = __expf(d1[nf][0] + bb0); e1 = __expf(d1[nf][1] + bb1);
            if (rw < N) { *(float2*)&out[rw * 64 + col] = make_float2(e0, e1); ssum += e0 + e1; }
            rw = base + qrow + 24;
            e0 = __expf(d1[nf][2] + bb0); e1 = __expf(d1[nf][3] + bb1);
            if (rw < N) { *(float2*)&out[rw * 64 + col] = make_float2(e0, e1); ssum += e0 + e1; }
        }
    }
    #pragma unroll
    for (int o = 16; o > 0; o >>= 1) ssum += __shfl_xor_sync(0xffffffffu, ssum, o);
    if (lane == 0) wsum[wid] = ssum;
    __syncthreads();
    if (t == 0) {
        float s = 0.f;
        #pragma unroll
        for (int i = 0; i < 8; i++) s += wsum[i];
        g_part[blockIdx.x] = s;
    }
}

// ------------- finish softmax -------------------------------------------------
__global__ void reduce_sum_kernel(int n) {
    __shared__ float ws[8];
    int t = threadIdx.x, lane = t & 31, wid = t >> 5;
    float s = 0.f;
    for (int i = t; i < n; i += blockDim.x) s += g_part[i];
    #pragma unroll
    for (int o = 16; o > 0; o >>= 1) s += __shfl_xor_sync(0xffffffffu, s, o);
    if (lane == 0) ws[wid] = s;
    __syncthreads();
    if (t == 0) {
        float r = 0.f;
        for (int i = 0; i < (int)(blockDim.x >> 5); i++) r += ws[i];
        g_scalar[1] = 1.0f / r;
    }
}

__global__ void normalize_kernel(float* __restrict__ out, int total) {
    float inv = g_scalar[1];
    int i = (blockIdx.x * blockDim.x + threadIdx.x) * 4;
    if (i + 3 < total) {
        float4 v = *(float4*)(out + i);
        v.x *= inv; v.y *= inv; v.z *= inv; v.w *= inv;
        *(float4*)(out + i) = v;
    } else {
        for (int j = i; j < total; j++) out[j] *= inv;
    }
}

// ---------------- launch ----------------------------------------------------
extern "C" void kernel_launch(void* const* d_in, const int* in_sizes, int n_in,
                              void* d_out, int out_size) {
    const float* x  = (const float*)d_in[0];
    const int*   ei = (const int*)d_in[1];
    int base = n_in - 8;   // last 8: W1,b1,W2,b2,Wo1,bo1,Wo2,bo2
    const float* W1  = (const float*)d_in[base + 0];
    const float* b1  = (const float*)d_in[base + 1];
    const float* W2  = (const float*)d_in[base + 2];
    const float* b2  = (const float*)d_in[base + 3];
    const float* Wo1 = (const float*)d_in[base + 4];
    const float* bo1 = (const float*)d_in[base + 5];
    const float* Wo2 = (const float*)d_in[base + 6];
    const float* bo2 = (const float*)d_in[base + 7];
    float* out = (float*)d_out;

    int N = in_sizes[0] / IN_DIM;
    int E = in_sizes[1] / 2;
    int nb_scan = (N + 1023) / 1024;
    bool evenE = (E % 2) == 0;

    static cudaStream_t s2 = nullptr;
    static cudaEvent_t evFork = nullptr, evDinv = nullptr, evJoin = nullptr;
    if (s2 == nullptr) {
        cudaStreamCreateWithFlags(&s2, cudaStreamNonBlocking);
        cudaEventCreateWithFlags(&evFork, cudaEventDisableTiming);
        cudaEventCreateWithFlags(&evDinv, cudaEventDisableTiming);
        cudaEventCreateWithFlags(&evJoin, cudaEventDisableTiming);
        cudaFuncSetAttribute(mlp_mma_kernel,
                             cudaFuncAttributeMaxDynamicSharedMemorySize, MLP_SMEM);
    }

    // fork: gemm1 on s2 overlaps the CSR build
    cudaEventRecord(evFork, 0);
    cudaStreamWaitEvent(s2, evFork, 0);
    int nWarpTiles = (N + 31) / 32;
    gemm1_kernel<<<(nWarpTiles + 7) / 8, 256, 0, s2>>>(x, W1, N);

    // main: CSR build up to dinv (hist also records per-edge slots)
    detect_zero_kernel<<<(N + 255) / 256, 256>>>((const unsigned int*)ei, 2 * E, N);
    if (evenE) hist_kernel<<<(E / 2 + 255) / 256, 256>>>(ei, E);
    else       hist_kernel_s<<<(E + 255) / 256, 256>>>(ei, E);
    scan1_kernel<<<nb_scan, 1024>>>(N);
    scan3a_kernel<<<(N + 255) / 256, 256>>>(N, E);
    cudaEventRecord(evDinv, 0);

    // s2: pack_h1 (needs gemm1 + dinv) overlaps fill on main
    cudaStreamWaitEvent(s2, evDinv, 0);
    pack_h1_kernel<<<(N + 255) / 256, 256, 0, s2>>>(N);
    cudaEventRecord(evJoin, s2);

    // main: CSR fill (atomic-free)
    if (evenE) fill_kernel<<<(E / 2 + 255) / 256, 256>>>(ei, E);
    else       fill_kernel_s<<<(E + 255) / 256, 256>>>(ei, E);

    // join
    cudaStreamWaitEvent(0, evJoin, 0);

    // GCN layer 2 + head: one node per warp, pipelined col loads
    int nblkNode = (N + 7) / 8;
    agg1_gemm2_kernel<<<nblkNode, 256>>>(b1, W2, N);
    agg2_kernel<<<nblkNode, 256>>>(b2, N);
    int nblkMlp = (N + 255) / 256;
    mlp_mma_kernel<<<nblkMlp, 256, MLP_SMEM>>>(Wo1, bo1, Wo2, bo2, out, N);

    // softmax finish
    int total = out_size;
    reduce_sum_kernel<<<1, 256>>>(nblkMlp);
    normalize_kernel<<<(total / 4 + 255) / 256, 256>>>(out, total);
}

// round 17
// speedup vs baseline: 1.0169x; 1.0169x over previous
#include <cuda_runtime.h>
#include <cuda_fp16.h>

#define NN 100000
#define EE 3200000
#define IN_DIM 256
#define H1 32
#define H2 64

typedef unsigned long long ull;

// ---- packed f32x2 helpers (Blackwell FFMA2) --------------------------------
__device__ __forceinline__ ull ffma2(ull a, ull b, ull c) {
    ull d;
    asm("fma.rn.f32x2 %0, %1, %2, %3;" : "=l"(d) : "l"(a), "l"(b), "l"(c));
    return d;
}
__device__ __forceinline__ float2 unpack2(ull v) {
    float2 r;
    asm("mov.b64 {%0, %1}, %2;" : "=f"(r.x), "=f"(r.y) : "l"(v));
    return r;
}

// ---- tf32 mma helpers -------------------------------------------------------
__device__ __forceinline__ unsigned cvt_tf32(float f) {
    unsigned u;
    asm("cvt.rna.tf32.f32 %0, %1;" : "=r"(u) : "f"(f));
    return u;
}
__device__ __forceinline__ void mma_tf32(float c[4], unsigned a0, unsigned a1,
                                         unsigned a2, unsigned a3,
                                         unsigned b0, unsigned b1) {
    asm("mma.sync.aligned.m16n8k8.row.col.f32.tf32.tf32.f32 "
        "{%0,%1,%2,%3},{%4,%5,%6,%7},{%8,%9},{%0,%1,%2,%3};"
        : "+f"(c[0]), "+f"(c[1]), "+f"(c[2]), "+f"(c[3])
        : "r"(a0), "r"(a1), "r"(a2), "r"(a3), "r"(b0), "r"(b1));
}
__device__ __forceinline__ unsigned comp4(uint4 v, int k) {
    return k == 0 ? v.x : k == 1 ? v.y : k == 2 ? v.z : v.w;
}

// ---------------- static device scratch -------------------------------------
__device__ __align__(256) float   g_h1[NN * H1];   // x@W1 (fp32, unscaled)
__device__ __align__(256) __half2 g_h1h[NN * 16];  // scaled h1, pairs (c, c+16)
__device__ __align__(256) __half2 g_h2h[NN * 32];  // (z1@W2)*dinv, pairs (c, c+32)
__device__ __align__(256) __half  g_z2p[NN * 64];  // z2, mma-fragment-permuted
__device__ int   g_cnt[NN];
__device__ int   g_rowptr[NN + 1];
__device__ int   g_col[EE];
__device__ int   g_off[EE];     // per-edge within-row slot (from hist)
__device__ float g_dinv[NN];
__device__ int   g_bsum[256];
__device__ float g_part[2048];
__device__ float g_scalar[2];
__device__ int   g_flag;        // 1 if edge index int64, 0 if int32

// ------------- detect edge dtype (tiny; g_cnt zeroed by previous agg1) ------
__global__ void detect_kernel(const unsigned int* __restrict__ w, int n_vals) {
    __shared__ unsigned int acc;
    if (threadIdx.x == 0) acc = 0u;
    __syncthreads();
    int K = n_vals < 2048 ? n_vals : 2048;
    unsigned int v = 0u;
    for (int j = threadIdx.x; j < K; j += blockDim.x) v |= w[2 * j + 1];
    atomicOr(&acc, v);
    __syncthreads();
    if (threadIdx.x == 0) g_flag = (acc == 0u) ? 1 : 0;
}

// ------------- histogram of dst (4 edges/thread) + per-edge slot ------------
__global__ void hist_kernel4(const int* __restrict__ buf, int E) {
    int e = (blockIdx.x * blockDim.x + threadIdx.x) * 4;
    if (e + 3 < E) {
        int d0, d1, d2, d3;
        if (g_flag) {
            int4 va = *(const int4*)&buf[2 * (E + e)];
            int4 vb = *(const int4*)&buf[2 * (E + e) + 4];
            d0 = va.x; d1 = va.z; d2 = vb.x; d3 = vb.z;
        } else {
            int4 v = *(const int4*)&buf[E + e];
            d0 = v.x; d1 = v.y; d2 = v.z; d3 = v.w;
        }
        int p0 = atomicAdd(&g_cnt[d0], 1);
        int p1 = atomicAdd(&g_cnt[d1], 1);
        int p2 = atomicAdd(&g_cnt[d2], 1);
        int p3 = atomicAdd(&g_cnt[d3], 1);
        *(int4*)&g_off[e] = make_int4(p0, p1, p2, p3);
    } else {
        for (int k = 0; e + k < E; k++) {
            int d = g_flag ? buf[2 * (E + e + k)] : buf[E + e + k];
            g_off[e + k] = atomicAdd(&g_cnt[d], 1);
        }
    }
}

__global__ void hist_kernel_s(const int* __restrict__ buf, int E) {
    int e = blockIdx.x * blockDim.x + threadIdx.x;
    if (e < E) {
        int d = g_flag ? buf[2 * (E + e)] : buf[E + e];
        g_off[e] = atomicAdd(&g_cnt[d], 1);
    }
}

// ------------- scan stage 1: per-chunk exclusive prefix + chunk totals ------
__global__ void scan1_kernel(int N) {
    __shared__ int sm[1024];
    int t = threadIdx.x;
    int i = blockIdx.x * 1024 + t;
    int x = (i < N) ? g_cnt[i] : 0;
    sm[t] = x;
    __syncthreads();
    for (int off = 1; off < 1024; off <<= 1) {
        int v = (t >= off) ? sm[t - off] : 0;
        __syncthreads();
        sm[t] += v;
        __syncthreads();
    }
    if (i < N) g_rowptr[i] = sm[t] - x;
    if (t == 1023) g_bsum[blockIdx.x] = sm[1023];
}

// ------------- scan stage 2 (merged): chunk-offset reduce + rowptr + dinv ---
__global__ void scan3a_kernel(int N, int E) {
    __shared__ int red[256];
    int t = threadIdx.x;
    int chunk = (blockIdx.x * 256) >> 10;
    red[t] = (t < chunk) ? g_bsum[t] : 0;
    __syncthreads();
    #pragma unroll
    for (int off = 128; off > 0; off >>= 1) {
        if (t < off) red[t] += red[t + off];
        __syncthreads();
    }
    int S = red[0];
    int i = blockIdx.x * 256 + t;
    if (i < N) {
        g_rowptr[i] = g_rowptr[i] + S;
        g_dinv[i]   = rsqrtf((float)(g_cnt[i] + 1));
        if (i == 0) g_rowptr[N] = E;
    }
}

// pack_h1: scale by dinv and pack to fp16 pairs (side stream, overlaps fill)
__global__ void pack_h1_kernel(int N) {
    int i = blockIdx.x * blockDim.x + threadIdx.x;
    if (i < N) {
        float di = g_dinv[i];
        float ch[32];
        const float4* h = (const float4*)&g_h1[i * H1];
        #pragma unroll
        for (int j = 0; j < 8; j++) {
            float4 v = h[j];
            ch[4 * j + 0] = v.x * di; ch[4 * j + 1] = v.y * di;
            ch[4 * j + 2] = v.z * di; ch[4 * j + 3] = v.w * di;
        }
        #pragma unroll
        for (int p = 0; p < 16; p++)
            g_h1h[i * 16 + p] = __floats2half2_rn(ch[p], ch[p + 16]);
    }
}

// ------------- GEMM1 via tf32 tensor cores (side stream) --------------------
__global__ void gemm1_kernel(const float* __restrict__ x,
                             const float* __restrict__ W1, int N) {
    __shared__ unsigned Bs[8192];   // [ks][nf][j][lane], 32 KB
    int t = threadIdx.x;
    for (int i = t; i < 8192; i += 256) {
        int lane2 = i & 31;
        int j  = (i >> 5) & 1;
        int nf = (i >> 6) & 3;
        int ks = i >> 8;
        int k = ks * 8 + (lane2 & 3) + j * 4;
        int n = nf * 8 + (lane2 >> 2);
        Bs[i] = cvt_tf32(W1[k * 32 + n]);
    }
    __syncthreads();
    int lane = t & 31, wid = t >> 5;
    int qrow = lane >> 2, qk = lane & 3;
    long r0 = (long)(blockIdx.x * 8 + wid) * 32;
    if (r0 >= N) return;
    long NL = N - 1;
    const float* p0 = x + (r0 + qrow      <= NL ? r0 + qrow      : NL) * 256 + qk;
    const float* p1 = x + (r0 + qrow + 8  <= NL ? r0 + qrow + 8  : NL) * 256 + qk;
    const float* p2 = x + (r0 + qrow + 16 <= NL ? r0 + qrow + 16 : NL) * 256 + qk;
    const float* p3 = x + (r0 + qrow + 24 <= NL ? r0 + qrow + 24 : NL) * 256 + qk;
    float c0[4][4] = {}, c1[4][4] = {};
    #pragma unroll 4
    for (int ks = 0; ks < 32; ks++) {
        int k0 = ks * 8;
        const unsigned* bp = &Bs[ks * 256 + lane];
        unsigned b00 = bp[0],   b01 = bp[32];
        unsigned b10 = bp[64],  b11 = bp[96];
        unsigned b20 = bp[128], b21 = bp[160];
        unsigned b30 = bp[192], b31 = bp[224];
        unsigned a0 = cvt_tf32(p0[k0]);
        unsigned a1 = cvt_tf32(p1[k0]);
        unsigned a2 = cvt_tf32(p0[k0 + 4]);
        unsigned a3 = cvt_tf32(p1[k0 + 4]);
        mma_tf32(c0[0], a0, a1, a2, a3, b00, b01);
        mma_tf32(c0[1], a0, a1, a2, a3, b10, b11);
        mma_tf32(c0[2], a0, a1, a2, a3, b20, b21);
        mma_tf32(c0[3], a0, a1, a2, a3, b30, b31);
        a0 = cvt_tf32(p2[k0]);
        a1 = cvt_tf32(p3[k0]);
        a2 = cvt_tf32(p2[k0 + 4]);
        a3 = cvt_tf32(p3[k0 + 4]);
        mma_tf32(c1[0], a0, a1, a2, a3, b00, b01);
        mma_tf32(c1[1], a0, a1, a2, a3, b10, b11);
        mma_tf32(c1[2], a0, a1, a2, a3, b20, b21);
        mma_tf32(c1[3], a0, a1, a2, a3, b30, b31);
    }
    long rw0 = r0 + qrow, rw1 = rw0 + 8, rw2 = rw0 + 16, rw3 = rw0 + 24;
    int cb = 2 * qk;
    #pragma unroll
    for (int nf = 0; nf < 4; nf++) {
        int col = nf * 8 + cb;
        if (rw0 < N) *(float2*)&g_h1[rw0 * 32 + col] = make_float2(c0[nf][0], c0[nf][1]);
        if (rw1 < N) *(float2*)&g_h1[rw1 * 32 + col] = make_float2(c0[nf][2], c0[nf][3]);
        if (rw2 < N) *(float2*)&g_h1[rw2 * 32 + col] = make_float2(c1[nf][0], c1[nf][1]);
        if (rw3 < N) *(float2*)&g_h1[rw3 * 32 + col] = make_float2(c1[nf][2], c1[nf][3]);
    }
}

// ------------- CSR fill (atomic-free, 4 edges/thread) -----------------------
__global__ void fill_kernel4(const int* __restrict__ buf, int E) {
    int e = (blockIdx.x * blockDim.x + threadIdx.x) * 4;
    if (e + 3 < E) {
        int s0, s1, s2, s3, d0, d1, d2, d3;
        if (g_flag) {
            int4 sa = *(const int4*)&buf[2 * e];
            int4 sb = *(const int4*)&buf[2 * e + 4];
            int4 da = *(const int4*)&buf[2 * (E + e)];
            int4 db = *(const int4*)&buf[2 * (E + e) + 4];
            s0 = sa.x; s1 = sa.z; s2 = sb.x; s3 = sb.z;
            d0 = da.x; d1 = da.z; d2 = db.x; d3 = db.z;
        } else {
            int4 sv = *(const int4*)&buf[e];
            int4 dv = *(const int4*)&buf[E + e];
            s0 = sv.x; s1 = sv.y; s2 = sv.z; s3 = sv.w;
            d0 = dv.x; d1 = dv.y; d2 = dv.z; d3 = dv.w;
        }
        int4 o = *(const int4*)&g_off[e];
        g_col[g_rowptr[d0] + o.x] = s0;
        g_col[g_rowptr[d1] + o.y] = s1;
        g_col[g_rowptr[d2] + o.z] = s2;
        g_col[g_rowptr[d3] + o.w] = s3;
    } else {
        for (int k = 0; e + k < E; k++) {
            int s, d;
            if (g_flag) { d = buf[2 * (E + e + k)]; s = buf[2 * (e + k)]; }
            else        { d = buf[E + e + k];       s = buf[e + k]; }
            g_col[g_rowptr[d] + g_off[e + k]] = s;
        }
    }
}

__global__ void fill_kernel_s(const int* __restrict__ buf, int E) {
    int e = blockIdx.x * blockDim.x + threadIdx.x;
    if (e < E) {
        int s, d;
        if (g_flag) { d = buf[2 * (E + e)]; s = buf[2 * e]; }
        else        { d = buf[E + e];       s = buf[e]; }
        g_col[g_rowptr[d] + g_off[e]] = s;
    }
}

// ------------- agg1: one node/warp; also zeroes g_cnt for next replay -------
__global__ void agg1_gemm2_kernel(const float* __restrict__ b1,
                                  const float* __restrict__ W2, int N) {
    __shared__ float2 Wp[H1 * 32];   // Wp[k*32+c] = (W2[k][c], W2[k][c+32])
    __shared__ float2 zd[8][32];     // duplicated z pairs per warp
    int t = threadIdx.x;
    int gid = blockIdx.x * blockDim.x + t;
    if (gid < N) g_cnt[gid] = 0;     // cnt dead after scan3a; pre-zero for next run
    for (int i = t; i < H1 * 32; i += blockDim.x) {
        int k = i >> 5, c2 = i & 31;
        Wp[i] = make_float2(W2[k * H2 + c2], W2[k * H2 + 32 + c2]);
    }
    __syncthreads();
    int lane = t & 31, wid = t >> 5;
    int c = lane & 15;
    int hb = (lane >> 4) << 4;   // 0 or 16
    int d = blockIdx.x * 8 + wid;
    if (d >= N) return;
    float bias0 = b1[c], bias1 = b1[c + 16];
    int beg = g_rowptr[d], end = g_rowptr[d + 1];
    float aAx = 0.f, aAy = 0.f, aBx = 0.f, aBy = 0.f;
    int e = beg;
    int cv = (e + 32 <= end) ? g_col[e + lane] : 0;
    for (; e + 32 <= end; ) {
        int cur = cv;
        int en = e + 32;
        if (en + 32 <= end) cv = g_col[en + lane];
        #pragma unroll
        for (int j = 0; j < 16; j += 2) {
            int s0 = __shfl_sync(0xffffffffu, cur, j + hb);
            int s1 = __shfl_sync(0xffffffffu, cur, j + 1 + hb);
            float2 f0 = __half22float2(g_h1h[s0 * 16 + c]);
            float2 f1 = __half22float2(g_h1h[s1 * 16 + c]);
            aAx += f0.x; aAy += f0.y;
            aBx += f1.x; aBy += f1.y;
        }
        e = en;
    }
    if (e < end) {
        int n = end - e;
        int rv = (e + lane < end) ? g_col[e + lane] : 0;
        int hodd = hb >> 4;                  // 0 or 1
        for (int j = 0; j < n; j += 2) {
            int idx = j + hodd;
            int s = __shfl_sync(0xffffffffu, rv, idx < n ? idx : 0);
            if (idx < n) {
                float2 f = __half22float2(g_h1h[s * 16 + c]);
                aAx += f.x; aAy += f.y;
            }
        }
    }
    float ax = aAx + aBx, ay = aAy + aBy;
    ax += __shfl_xor_sync(0xffffffffu, ax, 16);
    ay += __shfl_xor_sync(0xffffffffu, ay, 16);
    float2 sf = __half22float2(g_h1h[d * 16 + c]);   // self loop
    float di = g_dinv[d];
    float z0  = fmaxf(di * (ax + sf.x) + bias0, 0.f);
    float z16 = fmaxf(di * (ay + sf.y) + bias1, 0.f);
    zd[wid][c]      = make_float2(z0, z0);
    zd[wid][c + 16] = make_float2(z16, z16);
    __syncwarp();
    ull a2 = 0;
    #pragma unroll
    for (int k = 0; k < 32; k++)
        a2 = ffma2(*(const ull*)&zd[wid][k], *(const ull*)&Wp[k * 32 + lane], a2);
    float2 a = unpack2(a2);
    g_h2h[d * 32 + lane] = __floats2half2_rn(a.x * di, a.y * di);
}

// ------------- agg2: one node/warp -> z2 (fragment-permuted fp16) -----------
__global__ void agg2_kernel(const float* __restrict__ b2, int N) {
    __shared__ float bb[64];
    int t = threadIdx.x;
    if (t < 64) bb[t] = b2[t];
    __syncthreads();
    int lane = t & 31, wid = t >> 5;
    int d = blockIdx.x * 8 + wid;
    if (d >= N) return;
    float bias0 = bb[lane], bias1 = bb[lane + 32];
    int beg = g_rowptr[d], end = g_rowptr[d + 1];
    float2 self = __half22float2(g_h2h[d * 32 + lane]);
    float a00 = self.x, a10 = self.y;
    float a01 = 0.f, a11 = 0.f;
    int e = beg;
    int cv = (e + 32 <= end) ? g_col[e + lane] : 0;
    for (; e + 32 <= end; ) {
        int cur = cv;
        int en = e + 32;
        if (en + 32 <= end) cv = g_col[en + lane];
        #pragma unroll
        for (int j = 0; j < 32; j += 2) {
            int s0 = __shfl_sync(0xffffffffu, cur, j);
            int s1 = __shfl_sync(0xffffffffu, cur, j + 1);
            float2 f0 = __half22float2(g_h2h[s0 * 32 + lane]);
            float2 f1 = __half22float2(g_h2h[s1 * 32 + lane]);
            a00 += f0.x; a10 += f0.y;
            a01 += f1.x; a11 += f1.y;
        }
        e = en;
    }
    if (e < end) {
        int n = end - e;
        int rv = (e + lane < end) ? g_col[e + lane] : 0;
        int j = 0;
        for (; j + 2 <= n; j += 2) {
            int s0 = __shfl_sync(0xffffffffu, rv, j);
            int s1 = __shfl_sync(0xffffffffu, rv, j + 1);
            float2 f0 = __half22float2(g_h2h[s0 * 32 + lane]);
            float2 f1 = __half22float2(g_h2h[s1 * 32 + lane]);
            a00 += f0.x; a10 += f0.y;
            a01 += f1.x; a11 += f1.y;
        }
        if (j < n) {
            int s = __shfl_sync(0xffffffffu, rv, j);
            float2 f = __half22float2(g_h2h[s * 32 + lane]);
            a00 += f.x; a10 += f.y;
        }
    }
    float di = g_dinv[d];
    float t0 = fmaxf(di * (a00 + a01) + bias0, 0.f);
    float t1 = fmaxf(di * (a10 + a11) + bias1, 0.f);
    // fragment-permuted store: col = 8*ks + 4*hi + qk -> pos = qk*16 + ks*2 + hi
    int pos = (lane & 3) * 16 + (lane >> 3) * 2 + ((lane >> 2) & 1);
    g_z2p[d * 64 + pos]     = __float2half_rn(t0);   // col = lane
    g_z2p[d * 64 + pos + 8] = __float2half_rn(t1);   // col = lane + 32
}

// ------------- MLP head via tf32 MMA: out = exp(relu(z2@Wo1+bo1)@Wo2+bo2) ---
#define UPITCH 68
#define MLP_SMEM (8192 * 4 + 8 * 32 * UPITCH * 4 + 128 * 4)
__global__ __launch_bounds__(256, 2)
void mlp_mma_kernel(const float* __restrict__ Wo1, const float* __restrict__ bo1,
                    const float* __restrict__ Wo2, const float* __restrict__ bo2,
                    float* __restrict__ out, int N) {
    extern __shared__ unsigned msm[];
    unsigned* Bs1 = msm;                         // 4096 u32
    unsigned* Bs2 = msm + 4096;                  // 4096 u32
    float* us  = (float*)(msm + 8192);           // 8 * 32 * 68 floats
    float* b1s = us + 8 * 32 * UPITCH;           // 64
    float* b2s = b1s + 64;                       // 64
    __shared__ float wsum[8];
    int t = threadIdx.x;
    for (int i = t; i < 4096; i += 256) {
        int lane2 = i & 31;
        int j  = (i >> 5) & 1;
        int nf = (i >> 6) & 7;
        int ks = (i >> 9) & 7;
        int k = ks * 8 + (lane2 & 3) + j * 4;
        int n = nf * 8 + (lane2 >> 2);
        Bs1[i] = cvt_tf32(Wo1[k * 64 + n]);
        Bs2[i] = cvt_tf32(Wo2[k * 64 + n]);
    }
    if (t < 64) { b1s[t] = bo1[t]; b2s[t] = bo2[t]; }
    __syncthreads();
    int lane = t & 31, wid = t >> 5;
    int qrow = lane >> 2, qk = lane & 3;
    long base = (long)(blockIdx.x * 8 + wid) * 32;
    float ssum = 0.f;
    if (base < N) {
        long NL = N - 1;
        long r0 = base + qrow      <= NL ? base + qrow      : NL;
        long r1 = base + qrow + 8  <= NL ? base + qrow + 8  : NL;
        long r2 = base + qrow + 16 <= NL ? base + qrow + 16 : NL;
        long r3 = base + qrow + 24 <= NL ? base + qrow + 24 : NL;
        // vectorized fragment loads: 2x LDG.128 per row
        const uint4* zp = (const uint4*)g_z2p;
        uint4 Aa = zp[r0 * 8 + qk * 2], Ab = zp[r0 * 8 + qk * 2 + 1];
        uint4 Ba = zp[r1 * 8 + qk * 2], Bb = zp[r1 * 8 + qk * 2 + 1];
        uint4 Ca = zp[r2 * 8 + qk * 2], Cb = zp[r2 * 8 + qk * 2 + 1];
        uint4 Da = zp[r3 * 8 + qk * 2], Db = zp[r3 * 8 + qk * 2 + 1];
        float c0[8][4] = {}, c1[8][4] = {};
        #pragma unroll
        for (int ks = 0; ks < 8; ks++) {
            unsigned pA = ks < 4 ? comp4(Aa, ks) : comp4(Ab, ks - 4);
            unsigned pB = ks < 4 ? comp4(Ba, ks) : comp4(Bb, ks - 4);
            unsigned pC = ks < 4 ? comp4(Ca, ks) : comp4(Cb, ks - 4);
            unsigned pD = ks < 4 ? comp4(Da, ks) : comp4(Db, ks - 4);
            float2 fA = __half22float2(*(__half2*)&pA);
            float2 fB = __half22float2(*(__half2*)&pB);
            float2 fC = __half22float2(*(__half2*)&pC);
            float2 fD = __half22float2(*(__half2*)&pD);
            unsigned a0 = cvt_tf32(fA.x), a2 = cvt_tf32(fA.y);
            unsigned a1 = cvt_tf32(fB.x), a3 = cvt_tf32(fB.y);
            unsigned a4 = cvt_tf32(fC.x), a6 = cvt_tf32(fC.y);
            unsigned a5 = cvt_tf32(fD.x), a7 = cvt_tf32(fD.y);
            const unsigned* bp = &Bs1[ks * 512 + lane];
            #pragma unroll
            for (int nf = 0; nf < 8; nf++) {
                unsigned b0 = bp[nf * 64], b1 = bp[nf * 64 + 32];
                mma_tf32(c0[nf], a0, a1, a2, a3, b0, b1);
                mma_tf32(c1[nf], a4, a5, a6, a7, b0, b1);
            }
        }
        float* uw = us + wid * (32 * UPITCH);
        #pragma unroll
        for (int nf = 0; nf < 8; nf++) {
            int col = nf * 8 + 2 * qk;
            float bb0 = b1s[col], bb1 = b1s[col + 1];
            uw[qrow * UPITCH + col]            = fmaxf(c0[nf][0] + bb0, 0.f);
            uw[qrow * UPITCH + col + 1]        = fmaxf(c0[nf][1] + bb1, 0.f);
            uw[(qrow + 8) * UPITCH + col]      = fmaxf(c0[nf][2] + bb0, 0.f);
            uw[(qrow + 8) * UPITCH + col + 1]  = fmaxf(c0[nf][3] + bb1, 0.f);
            uw[(qrow + 16) * UPITCH + col]     = fmaxf(c1[nf][0] + bb0, 0.f);
            uw[(qrow + 16) * UPITCH + col + 1] = fmaxf(c1[nf][1] + bb1, 0.f);
            uw[(qrow + 24) * UPITCH + col]     = fmaxf(c1[nf][2] + bb0, 0.f);
            uw[(qrow + 24) * UPITCH + col + 1] = fmaxf(c1[nf][3] + bb1, 0.f);
        }
        __syncwarp();
        float d0[8][4] = {}, d1[8][4] = {};
        #pragma unroll
        for (int ks = 0; ks < 8; ks++) {
            int k0 = ks * 8;
            unsigned a0 = cvt_tf32(uw[qrow * UPITCH + k0 + qk]);
            unsigned a1 = cvt_tf32(uw[(qrow + 8) * UPITCH + k0 + qk]);
            unsigned a2 = cvt_tf32(uw[qrow * UPITCH + k0 + qk + 4]);
            unsigned a3 = cvt_tf32(uw[(qrow + 8) * UPITCH + k0 + qk + 4]);
            unsigned a4 = cvt_tf32(uw[(qrow + 16) * UPITCH + k0 + qk]);
            unsigned a5 = cvt_tf32(uw[(qrow + 24) * UPITCH + k0 + qk]);
            unsigned a6 = cvt_tf32(uw[(qrow + 16) * UPITCH + k0 + qk + 4]);
            unsigned a7 = cvt_tf32(uw[(qrow + 24) * UPITCH + k0 + qk + 4]);
            const unsigned* bp = &Bs2[ks * 512 + lane];
            #pragma unroll
            for (int nf = 0; nf < 8; nf++) {
                unsigned b0 = bp[nf * 64], b1 = bp[nf * 64 + 32];
                mma_tf32(d0[nf], a0, a1, a2, a3, b0, b1);
                mma_tf32(d1[nf], a4, a5, a6, a7, b0, b1);
            }
        }
        #pragma unroll
        for (int nf = 0; nf < 8; nf++) {
            int col = nf * 8 + 2 * qk;
            float bb0 = b2s[col], bb1 = b2s[col + 1];
            long rw = base + qrow;
            float e0 = __expf(d0[nf][0] + bb0), e1 = __expf(d0[nf][1] + bb1);
            if (rw < N) { *(float2*)&out[rw * 64 + col] = make_float2(e0, e1); ssum += e0 + e1; }
            rw = base + qrow + 8;
            e0 = __expf(d0[nf][2] + bb0); e1 = __expf(d0[nf][3] + bb1);
            if (rw < N) { *(float2*)&out[rw * 64 + col] = make_float2(e0, e1); ssum += e0 + e1; }
            rw = base + qrow + 16;
            e0 = __expf(d1[nf][0] + bb0); e1 = __expf(d1[nf][1] + bb1);
            if (rw < N) { *(float2*)&out[rw * 64 + col] = make_float2(e0, e1); ssum += e0 + e1; }
            rw = base + qrow + 24;
            e0 = __expf(d1[nf][2] + bb0); e1 = __expf(d1[nf][3] + bb1);
            if (rw < N) { *(float2*)&out[rw * 64 + col] = make_float2(e0, e1); ssum += e0 + e1; }
        }
    }
    #pragma unroll
    for (int o = 16; o > 0; o >>= 1) ssum += __shfl_xor_sync(0xffffffffu, ssum, o);
    if (lane == 0) wsum[wid] = ssum;
    __syncthreads();
    if (t == 0) {
        float s = 0.f;
        #pragma unroll
        for (int i = 0; i < 8; i++) s += wsum[i];
        g_part[blockIdx.x] = s;
    }
}

// ------------- finish softmax -------------------------------------------------
__global__ void reduce_sum_kernel(int n) {
    __shared__ float ws[8];
    int t = threadIdx.x, lane = t & 31, wid = t >> 5;
    float s = 0.f;
    for (int i = t; i < n; i += blockDim.x) s += g_part[i];
    #pragma unroll
    for (int o = 16; o > 0; o >>= 1) s += __shfl_xor_sync(0xffffffffu, s, o);
    if (lane == 0) ws[wid] = s;
    __syncthreads();
    if (t == 0) {
        float r = 0.f;
        for (int i = 0; i < (int)(blockDim.x >> 5); i++) r += ws[i];
        g_scalar[1] = 1.0f / r;
    }
}

__global__ void normalize_kernel(float* __restrict__ out, int total) {
    float inv = g_scalar[1];
    int i = (blockIdx.x * blockDim.x + threadIdx.x) * 4;
    if (i + 3 < total) {
        float4 v = *(float4*)(out + i);
        v.x *= inv; v.y *= inv; v.z *= inv; v.w *= inv;
        *(float4*)(out + i) = v;
    } else {
        for (int j = i; j < total; j++) out[j] *= inv;
    }
}

// ---------------- launch ----------------------------------------------------
extern "C" void kernel_launch(void* const* d_in, const int* in_sizes, int n_in,
                              void* d_out, int out_size) {
    const float* x  = (const float*)d_in[0];
    const int*   ei = (const int*)d_in[1];
    int base = n_in - 8;   // last 8: W1,b1,W2,b2,Wo1,bo1,Wo2,bo2
    const float* W1  = (const float*)d_in[base + 0];
    const float* b1  = (const float*)d_in[base + 1];
    const float* W2  = (const float*)d_in[base + 2];
    const float* b2  = (const float*)d_in[base + 3];
    const float* Wo1 = (const float*)d_in[base + 4];
    const float* bo1 = (const float*)d_in[base + 5];
    const float* Wo2 = (const float*)d_in[base + 6];
    const float* bo2 = (const float*)d_in[base + 7];
    float* out = (float*)d_out;

    int N = in_sizes[0] / IN_DIM;
    int E = in_sizes[1] / 2;
    int nb_scan = (N + 1023) / 1024;
    bool e4 = (E & 3) == 0;

    static cudaStream_t s2 = nullptr;
    static cudaEvent_t evFork = nullptr, evDinv = nullptr, evJoin = nullptr;
    if (s2 == nullptr) {
        cudaStreamCreateWithFlags(&s2, cudaStreamNonBlocking);
        cudaEventCreateWithFlags(&evFork, cudaEventDisableTiming);
        cudaEventCreateWithFlags(&evDinv, cudaEventDisableTiming);
        cudaEventCreateWithFlags(&evJoin, cudaEventDisableTiming);
        cudaFuncSetAttribute(mlp_mma_kernel,
                             cudaFuncAttributeMaxDynamicSharedMemorySize, MLP_SMEM);
    }

    // fork: gemm1 on s2 overlaps the CSR build
    cudaEventRecord(evFork, 0);
    cudaStreamWaitEvent(s2, evFork, 0);
    int nWarpTiles = (N + 31) / 32;
    gemm1_kernel<<<(nWarpTiles + 7) / 8, 256, 0, s2>>>(x, W1, N);

    // main: CSR build up to dinv (g_cnt pre-zeroed by previous run's agg1)
    detect_kernel<<<1, 256>>>((const unsigned int*)ei, 2 * E);
    if (e4) hist_kernel4<<<(E / 4 + 255) / 256, 256>>>(ei, E);
    else    hist_kernel_s<<<(E + 255) / 256, 256>>>(ei, E);
    scan1_kernel<<<nb_scan, 1024>>>(N);
    scan3a_kernel<<<(N + 255) / 256, 256>>>(N, E);
    cudaEventRecord(evDinv, 0);

    // s2: pack_h1 (needs gemm1 + dinv) overlaps fill on main
    cudaStreamWaitEvent(s2, evDinv, 0);
    pack_h1_kernel<<<(N + 255) / 256, 256, 0, s2>>>(N);
    cudaEventRecord(evJoin, s2);

    // main: CSR fill (atomic-free)
    if (e4) fill_kernel4<<<(E / 4 + 255) / 256, 256>>>(ei, E);
    else    fill_kernel_s<<<(E + 255) / 256, 256>>>(ei, E);

    // join
    cudaStreamWaitEvent(0, evJoin, 0);

    // GCN layer 2 + head
    int nblkNode = (N + 7) / 8;
    agg1_gemm2_kernel<<<nblkNode, 256>>>(b1, W2, N);
    agg2_kernel<<<nblkNode, 256>>>(b2, N);
    int nblkMlp = (N + 255) / 256;
    mlp_mma_kernel<<<nblkMlp, 256, MLP_SMEM>>>(Wo1, bo1, Wo2, bo2, out, N);

    // softmax finish
    int total = out_size;
    reduce_sum_kernel<<<1, 256>>>(nblkMlp);
    normalize_kernel<<<(total / 4 + 255) / 256, 256>>>(out, total);
}